// round 2
// baseline (speedup 1.0000x reference)
#include <cuda_runtime.h>
#include <cstdint>

// Problem shape (fixed): x [T,B,C,H,W], T=4,B=16,C=512,H=W=32 -> N=1024
#define TT 4
#define BB 16
#define CC 512
#define NN 1024
#define HEADS 8
#define DD 64
#define VTH 1.0f

#define BCN  ((size_t)BB * CC * NN)          // 8,388,608
#define TBCN ((size_t)TT * BB * CC * NN)     // 33,554,432

// ---------------- scratch (static device globals; no runtime allocation) ----
__device__ float g_Y[3ull * TBCN];   // pre-LIF conv outputs q,k,v
__device__ float g_S[3ull * TBCN];   // spikes q,k,v
__device__ float g_att[TBCN];        // attention pre-LIF
__device__ float g_Sa[TBCN];         // attention spikes
__device__ float g_P[TBCN];          // proj conv output
__device__ float g_kv[(size_t)TT * BB * HEADS * DD * DD]; // 2M floats

// ---------------------------------------------------------------------------
// Packed fp32x2 FMA (sm_100+). Lane-wise IEEE fp32 FMA: bit-identical to FFMA,
// 2 FLOP-pairs per instruction on the fma pipe.
// ---------------------------------------------------------------------------
__device__ __forceinline__ unsigned long long ffma2(unsigned long long a,
                                                    unsigned long long b,
                                                    unsigned long long c)
{
    unsigned long long d;
    asm("fma.rn.f32x2 %0, %1, %2, %3;" : "=l"(d) : "l"(a), "l"(b), "l"(c));
    return d;
}

__device__ __forceinline__ float2 unpack2(unsigned long long v)
{
    float2 f;
    asm("mov.b64 {%0, %1}, %2;" : "=f"(f.x), "=f"(f.y) : "l"(v));
    return f;
}

// ---------------------------------------------------------------------------
// Fused conv1x1 GEMM: Y_w[o,n] = sum_c W_w[o,c] * X[c,n] + b_w[o]
// per (t,b): X is [C,N] slice. Tile 64x64, K-tile 16, 256 thr, 4x4 microtile.
// NW=3 shares the X tile across three weight matrices.
// Inner product uses fma.rn.f32x2: W stored pre-duplicated (w,w) in smem so
// each FFMA2 consumes a broadcast weight pair against an n-pair of X.
// ---------------------------------------------------------------------------
template <int NW>
__global__ __launch_bounds__(256)
void conv1x1_gemm(const float* __restrict__ Xall,
                  const float* __restrict__ W0, const float* __restrict__ W1,
                  const float* __restrict__ W2,
                  const float* __restrict__ b0, const float* __restrict__ b1,
                  const float* __restrict__ b2,
                  float* __restrict__ Y0, float* __restrict__ Y1,
                  float* __restrict__ Y2)
{
    constexpr int BM = 64, BN = 64, BK = 16;
    const int tb = blockIdx.z;
    const int n0 = blockIdx.x * BN;
    const int o0 = blockIdx.y * BM;
    const float* X = Xall + (size_t)tb * CC * NN;

    __shared__ __align__(16) float  Xs[BK][BN];       // [k][n]
    __shared__ __align__(16) float2 Wd[NW][BK][BM];   // [k][o] duplicated pairs

    const int tid = threadIdx.x;
    const int tx = tid & 15;       // n microtile (4 floats = 2 pairs)
    const int ty = tid >> 4;       // o microtile (4 outputs)

    // acc[w][i*2+p]: output row i (0..3), n-pair p (0..1), packed f32x2
    unsigned long long acc[NW][8];
#pragma unroll
    for (int w = 0; w < NW; w++)
#pragma unroll
        for (int q = 0; q < 8; q++) acc[w][q] = 0ull;

    const int xr = tid >> 4;             // 0..15 (k row)
    const int xc = (tid & 15) * 4;       // 0..60 (n col)
    const int wo = tid >> 2;             // 0..63 (o row)
    const int wk = (tid & 3) * 4;        // 0..12 (k col)

    const float* Wp_[3] = {W0, W1, W2};

    for (int c0 = 0; c0 < CC; c0 += BK) {
        // load X tile (coalesced float4)
        float4 xv = *(const float4*)(X + (size_t)(c0 + xr) * NN + n0 + xc);
        *(float4*)(&Xs[xr][xc]) = xv;
        // load W tiles, transpose + duplicate into [k][o] pairs
#pragma unroll
        for (int w = 0; w < NW; w++) {
            float4 wv = *(const float4*)(Wp_[w] + (size_t)(o0 + wo) * CC + c0 + wk);
            Wd[w][wk + 0][wo] = make_float2(wv.x, wv.x);
            Wd[w][wk + 1][wo] = make_float2(wv.y, wv.y);
            Wd[w][wk + 2][wo] = make_float2(wv.z, wv.z);
            Wd[w][wk + 3][wo] = make_float2(wv.w, wv.w);
        }
        __syncthreads();
#pragma unroll
        for (int kk = 0; kk < BK; kk++) {
            const ulonglong2 xa = *(const ulonglong2*)(&Xs[kk][tx * 4]);
#pragma unroll
            for (int w = 0; w < NW; w++) {
                const ulonglong2 wA = *(const ulonglong2*)(&Wd[w][kk][ty * 4]);
                const ulonglong2 wB = *(const ulonglong2*)(&Wd[w][kk][ty * 4 + 2]);
                acc[w][0] = ffma2(wA.x, xa.x, acc[w][0]);
                acc[w][1] = ffma2(wA.x, xa.y, acc[w][1]);
                acc[w][2] = ffma2(wA.y, xa.x, acc[w][2]);
                acc[w][3] = ffma2(wA.y, xa.y, acc[w][3]);
                acc[w][4] = ffma2(wB.x, xa.x, acc[w][4]);
                acc[w][5] = ffma2(wB.x, xa.y, acc[w][5]);
                acc[w][6] = ffma2(wB.y, xa.x, acc[w][6]);
                acc[w][7] = ffma2(wB.y, xa.y, acc[w][7]);
            }
        }
        __syncthreads();
    }

    const float* bp_[3] = {b0, b1, b2};
    float* Yp_[3] = {Y0, Y1, Y2};
#pragma unroll
    for (int w = 0; w < NW; w++) {
#pragma unroll
        for (int i = 0; i < 4; i++) {
            const int o = o0 + ty * 4 + i;
            const float bb = bp_[w][o];
            const float2 f01 = unpack2(acc[w][i * 2 + 0]);
            const float2 f23 = unpack2(acc[w][i * 2 + 1]);
            float4 r;
            r.x = f01.x + bb;
            r.y = f01.y + bb;
            r.z = f23.x + bb;
            r.w = f23.y + bb;
            *(float4*)(Yp_[w] + ((size_t)tb * CC + o) * NN + n0 + tx * 4) = r;
        }
    }
}

// ---------------------------------------------------------------------------
// LIF over T (elementwise). which: 0..2 -> g_Y->g_S ; 3 -> g_att->g_Sa
// v += (x - v)/2 ; spike v>=1 ; hard reset.
// ---------------------------------------------------------------------------
__global__ void lif_kernel(int base)
{
    const int which = base + blockIdx.y;
    const float* in;
    float* out;
    if (which < 3) {
        in = g_Y + (size_t)which * TBCN;
        out = g_S + (size_t)which * TBCN;
    } else {
        in = g_att;
        out = g_Sa;
    }
    const size_t i = (size_t)blockIdx.x * blockDim.x + threadIdx.x;
    if (i >= BCN) return;
    float v = 0.f;
#pragma unroll
    for (int t = 0; t < TT; t++) {
        float xx = in[(size_t)t * BCN + i];
        v = v + (xx - v) * 0.5f;
        float s = (v >= VTH) ? 1.f : 0.f;
        out[(size_t)t * BCN + i] = s;
        v = (s != 0.f) ? 0.f : v;
    }
}

// ---------------------------------------------------------------------------
// kv[tbh][d][e] = sum_n Sk[h*64+d, n] * Sv[h*64+e, n]     (exact: integer counts)
// one block per (t,b,h); 64x64 output, K = N = 1024 in chunks of 32.
// ---------------------------------------------------------------------------
__global__ __launch_bounds__(256)
void kv_kernel()
{
    const int tbh = blockIdx.x;          // 512
    const int tb = tbh >> 3;
    const int h = tbh & 7;
    const float* K_ = g_S + 1ull * TBCN + ((size_t)tb * CC + h * DD) * NN;
    const float* V_ = g_S + 2ull * TBCN + ((size_t)tb * CC + h * DD) * NN;

    __shared__ __align__(16) float KsT[32][DD + 4];  // [n][d]
    __shared__ __align__(16) float VsT[32][DD + 4];

    const int tid = threadIdx.x;
    const int tx = tid & 15, ty = tid >> 4;

    float acc[4][4] = {};

    for (int nb = 0; nb < NN; nb += 32) {
#pragma unroll
        for (int r = 0; r < 2; r++) {
            int fid = r * 256 + tid;
            int dd = fid >> 3;
            int ng = (fid & 7) * 4;
            float4 k4 = *(const float4*)(K_ + (size_t)dd * NN + nb + ng);
            KsT[ng + 0][dd] = k4.x; KsT[ng + 1][dd] = k4.y;
            KsT[ng + 2][dd] = k4.z; KsT[ng + 3][dd] = k4.w;
            float4 v4 = *(const float4*)(V_ + (size_t)dd * NN + nb + ng);
            VsT[ng + 0][dd] = v4.x; VsT[ng + 1][dd] = v4.y;
            VsT[ng + 2][dd] = v4.z; VsT[ng + 3][dd] = v4.w;
        }
        __syncthreads();
#pragma unroll
        for (int nn = 0; nn < 32; nn++) {
            float4 kf = *(const float4*)(&KsT[nn][ty * 4]);
            float4 vf = *(const float4*)(&VsT[nn][tx * 4]);
            float ka[4] = {kf.x, kf.y, kf.z, kf.w};
            float va[4] = {vf.x, vf.y, vf.z, vf.w};
#pragma unroll
            for (int i = 0; i < 4; i++)
#pragma unroll
                for (int j = 0; j < 4; j++)
                    acc[i][j] += ka[i] * va[j];
        }
        __syncthreads();
    }

    float* kvout = g_kv + (size_t)tbh * DD * DD;
#pragma unroll
    for (int i = 0; i < 4; i++) {
        float4 r = {acc[i][0], acc[i][1], acc[i][2], acc[i][3]};
        *(float4*)(kvout + (size_t)(ty * 4 + i) * DD + tx * 4) = r;
    }
}

// ---------------------------------------------------------------------------
// att[t,b, h*64+e, n] = 0.125 * sum_d Sq[h*64+d, n] * kv[d][e]   (exact)
// block = (n-tile of 64) x (t,b,h). 64x64 tile, K=64.
// ---------------------------------------------------------------------------
__global__ __launch_bounds__(256)
void attn_out_kernel()
{
    const int tbh = blockIdx.y;
    const int tb = tbh >> 3;
    const int h = tbh & 7;
    const int n0 = blockIdx.x * 64;
    const float* Q_ = g_S + ((size_t)tb * CC + h * DD) * NN;
    const float* kvp = g_kv + (size_t)tbh * DD * DD;

    __shared__ __align__(16) float kvs[DD][DD + 4];  // [d][e]
    __shared__ __align__(16) float Qs[16][64];       // [d][n]

    const int tid = threadIdx.x;
    const int tx = tid & 15, ty = tid >> 4;

    // load whole kv (4096 floats = 4 float4 per thread)
#pragma unroll
    for (int r = 0; r < 4; r++) {
        int fid = r * 256 + tid;
        int dd = fid >> 4;
        int eg = (fid & 15) * 4;
        float4 v = *(const float4*)(kvp + (size_t)dd * DD + eg);
        *(float4*)(&kvs[dd][eg]) = v;
    }
    __syncthreads();

    float acc[4][4] = {};  // [e][n]

    for (int d0 = 0; d0 < DD; d0 += 16) {
        int qr = tid >> 4;
        int qc = (tid & 15) * 4;
        float4 qv = *(const float4*)(Q_ + (size_t)(d0 + qr) * NN + n0 + qc);
        *(float4*)(&Qs[qr][qc]) = qv;
        __syncthreads();
#pragma unroll
        for (int kk = 0; kk < 16; kk++) {
            float4 qf = *(const float4*)(&Qs[kk][tx * 4]);
            float4 kf = *(const float4*)(&kvs[d0 + kk][ty * 4]);
            float qa[4] = {qf.x, qf.y, qf.z, qf.w};
            float ka[4] = {kf.x, kf.y, kf.z, kf.w};
#pragma unroll
            for (int i = 0; i < 4; i++)
#pragma unroll
                for (int j = 0; j < 4; j++)
                    acc[i][j] += ka[i] * qa[j];
        }
        __syncthreads();
    }

#pragma unroll
    for (int i = 0; i < 4; i++) {
        const int e = ty * 4 + i;
        float4 r;
        r.x = acc[i][0] * 0.125f;
        r.y = acc[i][1] * 0.125f;
        r.z = acc[i][2] * 0.125f;
        r.w = acc[i][3] * 0.125f;
        *(float4*)(g_att + ((size_t)tb * CC + h * DD + e) * NN + n0 + tx * 4) = r;
    }
}

// ---------------------------------------------------------------------------
// conn LIF: v += ((proj + x) - v)/2 ; spike; reset. writes final output.
// ---------------------------------------------------------------------------
__global__ void connlif_kernel(const float* __restrict__ x, float* __restrict__ out)
{
    const size_t i = (size_t)blockIdx.x * blockDim.x + threadIdx.x;
    if (i >= BCN) return;
    float v = 0.f;
#pragma unroll
    for (int t = 0; t < TT; t++) {
        float p = g_P[(size_t)t * BCN + i];
        float xx = x[(size_t)t * BCN + i];
        float chg = p + xx;
        v = v + (chg - v) * 0.5f;
        float s = (v >= VTH) ? 1.f : 0.f;
        out[(size_t)t * BCN + i] = s;
        v = (s != 0.f) ? 0.f : v;
    }
}

// ---------------------------------------------------------------------------
extern "C" void kernel_launch(void* const* d_in, const int* in_sizes, int n_in,
                              void* d_out, int out_size)
{
    const float* x  = (const float*)d_in[0];
    const float* Wq = (const float*)d_in[1];
    const float* bq = (const float*)d_in[2];
    const float* Wk = (const float*)d_in[3];
    const float* bk = (const float*)d_in[4];
    const float* Wv = (const float*)d_in[5];
    const float* bv = (const float*)d_in[6];
    const float* Wp = (const float*)d_in[7];
    const float* bp = (const float*)d_in[8];
    float* out = (float*)d_out;

    void *pY = nullptr, *pSa = nullptr, *pP = nullptr;
    cudaGetSymbolAddress(&pY, g_Y);
    cudaGetSymbolAddress(&pSa, g_Sa);
    cudaGetSymbolAddress(&pP, g_P);
    float* Yf = (float*)pY;

    const dim3 gemm_grid(NN / 64, CC / 64, TT * BB);  // (16, 8, 64)
    const int lif_blocks = (int)(BCN / 256);          // 32768

    // 1. fused QKV conv GEMM
    conv1x1_gemm<3><<<gemm_grid, 256>>>(x, Wq, Wk, Wv, bq, bk, bv,
                                        Yf, Yf + TBCN, Yf + 2ull * TBCN);
    // 2. LIF on q,k,v
    lif_kernel<<<dim3(lif_blocks, 3), 256>>>(0);
    // 3. kv = K^T V per head
    kv_kernel<<<TT * BB * HEADS, 256>>>();
    // 4. out = Q @ kv * SCALE
    attn_out_kernel<<<dim3(NN / 64, TT * BB * HEADS), 256>>>();
    // 5. LIF on attention output
    lif_kernel<<<dim3(lif_blocks, 1), 256>>>(3);
    // 6. proj conv GEMM
    conv1x1_gemm<1><<<gemm_grid, 256>>>((const float*)pSa, Wp, nullptr, nullptr,
                                        bp, nullptr, nullptr,
                                        (float*)pP, nullptr, nullptr);
    // 7. connecting LIF with identity shortcut -> final spikes
    connlif_kernel<<<lif_blocks, 256>>>(x, out);
}

// round 7
// speedup vs baseline: 1.4298x; 1.4298x over previous
#include <cuda_runtime.h>
#include <cstdint>

// Problem shape (fixed): x [T,B,C,H,W], T=4,B=16,C=512,H=W=32 -> N=1024
#define TT 4
#define BB 16
#define CC 512
#define NN 1024
#define HEADS 8
#define DD 64
#define VTH 1.0f

#define BCN  ((size_t)BB * CC * NN)          // 8,388,608
#define TBCN ((size_t)TT * BB * CC * NN)     // 33,554,432

// ---------------- scratch (static device globals; no runtime allocation) ----
__device__ float g_S[3ull * TBCN];   // spikes q,k,v
__device__ float g_Sa[TBCN];         // attention spikes
__device__ float g_kv[(size_t)TT * BB * HEADS * DD * DD];

// ---------------------------------------------------------------------------
// Fused QKV conv GEMM + LIF.  Per block: (o-tile 64, n-tile 64, b), loop t.
// GEMM inner loop is IDENTICAL (bit-exact) to the round-1 kernel: sequential
// k order per output, 4x4 microtile, BK=16. Membrane state lives in smem.
// Dynamic smem: Xs[16*64] + Ws[3*16*68] + V[3*256*16] floats = 66304 B.
// ---------------------------------------------------------------------------
__global__ __launch_bounds__(256)
void qkv_lif_kernel(const float* __restrict__ Xall,
                    const float* __restrict__ W0, const float* __restrict__ W1,
                    const float* __restrict__ W2,
                    const float* __restrict__ b0, const float* __restrict__ b1,
                    const float* __restrict__ b2)
{
    extern __shared__ float sm[];
    float* Xs = sm;                    // [16][64]
    float* Ws = sm + 1024;             // [3][16][68]
    float* Vs = sm + 1024 + 3264;      // [3][256*16]

    const int b = blockIdx.z;
    const int n0 = blockIdx.x * 64;
    const int o0 = blockIdx.y * 64;

    const int tid = threadIdx.x;
    const int tx = tid & 15;       // n microtile
    const int ty = tid >> 4;       // o microtile

    const int xr = tid >> 4;             // 0..15 (k row)
    const int xc = (tid & 15) * 4;       // 0..60 (n col)
    const int wo = tid >> 2;             // 0..63 (o row)
    const int wk = (tid & 3) * 4;        // 0..12 (k col)

    const float* Wp_[3] = {W0, W1, W2};
    const float* bp_[3] = {b0, b1, b2};

    // bias per owned output row (hoisted)
    float bb[3][4];
#pragma unroll
    for (int w = 0; w < 3; w++)
#pragma unroll
        for (int i = 0; i < 4; i++) bb[w][i] = bp_[w][o0 + ty * 4 + i];

    for (int t = 0; t < TT; t++) {
        const float* X = Xall + ((size_t)(t * BB + b)) * CC * NN;

        float acc[3][4][4];
#pragma unroll
        for (int w = 0; w < 3; w++)
#pragma unroll
            for (int i = 0; i < 4; i++)
#pragma unroll
                for (int j = 0; j < 4; j++) acc[w][i][j] = 0.f;

        for (int c0 = 0; c0 < CC; c0 += 16) {
            float4 xv = *(const float4*)(X + (size_t)(c0 + xr) * NN + n0 + xc);
            *(float4*)(&Xs[xr * 64 + xc]) = xv;
#pragma unroll
            for (int w = 0; w < 3; w++) {
                float4 wv = *(const float4*)(Wp_[w] + (size_t)(o0 + wo) * CC + c0 + wk);
                Ws[(w * 16 + wk + 0) * 68 + wo] = wv.x;
                Ws[(w * 16 + wk + 1) * 68 + wo] = wv.y;
                Ws[(w * 16 + wk + 2) * 68 + wo] = wv.z;
                Ws[(w * 16 + wk + 3) * 68 + wo] = wv.w;
            }
            __syncthreads();
#pragma unroll
            for (int kk = 0; kk < 16; kk++) {
                float4 xf = *(const float4*)(&Xs[kk * 64 + tx * 4]);
                float xfa[4] = {xf.x, xf.y, xf.z, xf.w};
#pragma unroll
                for (int w = 0; w < 3; w++) {
                    float4 wf = *(const float4*)(&Ws[(w * 16 + kk) * 68 + ty * 4]);
                    float wfa[4] = {wf.x, wf.y, wf.z, wf.w};
#pragma unroll
                    for (int i = 0; i < 4; i++)
#pragma unroll
                        for (int j = 0; j < 4; j++)
                            acc[w][i][j] += wfa[i] * xfa[j];
                }
            }
            __syncthreads();
        }

        // epilogue: bias + LIF update + spike write
#pragma unroll
        for (int w = 0; w < 3; w++) {
            float* out = g_S + (size_t)w * TBCN + (size_t)t * BCN
                         + ((size_t)b * CC) * NN;
#pragma unroll
            for (int i = 0; i < 4; i++) {
                const int o = o0 + ty * 4 + i;
                float4 r;
                float vv[4];
#pragma unroll
                for (int j = 0; j < 4; j++) {
                    const int vi = (w * 4096) + tid * 16 + i * 4 + j;
                    float v = (t == 0) ? 0.f : Vs[vi];
                    float xx = acc[w][i][j] + bb[w][i];
                    v = v + (xx - v) * 0.5f;
                    float s = (v >= VTH) ? 1.f : 0.f;
                    vv[j] = (s != 0.f) ? 0.f : v;
                    Vs[vi] = vv[j];
                    ((float*)&r)[j] = s;
                }
                *(float4*)(out + (size_t)o * NN + n0 + tx * 4) = r;
            }
        }
    }
}

// ---------------------------------------------------------------------------
// kv[tbh][d][e] = sum_n Sk[h*64+d, n] * Sv[h*64+e, n]   (exact integer counts)
// ---------------------------------------------------------------------------
__global__ __launch_bounds__(256)
void kv_kernel()
{
    const int tbh = blockIdx.x;
    const int tb = tbh >> 3;
    const int h = tbh & 7;
    const float* K_ = g_S + 1ull * TBCN + ((size_t)tb * CC + h * DD) * NN;
    const float* V_ = g_S + 2ull * TBCN + ((size_t)tb * CC + h * DD) * NN;

    __shared__ __align__(16) float KsT[32][DD + 4];
    __shared__ __align__(16) float VsT[32][DD + 4];

    const int tid = threadIdx.x;
    const int tx = tid & 15, ty = tid >> 4;
    float acc[4][4] = {};

    for (int nb = 0; nb < NN; nb += 32) {
#pragma unroll
        for (int r = 0; r < 2; r++) {
            int fid = r * 256 + tid;
            int dd = fid >> 3;
            int ng = (fid & 7) * 4;
            float4 k4 = *(const float4*)(K_ + (size_t)dd * NN + nb + ng);
            KsT[ng + 0][dd] = k4.x; KsT[ng + 1][dd] = k4.y;
            KsT[ng + 2][dd] = k4.z; KsT[ng + 3][dd] = k4.w;
            float4 v4 = *(const float4*)(V_ + (size_t)dd * NN + nb + ng);
            VsT[ng + 0][dd] = v4.x; VsT[ng + 1][dd] = v4.y;
            VsT[ng + 2][dd] = v4.z; VsT[ng + 3][dd] = v4.w;
        }
        __syncthreads();
#pragma unroll
        for (int nn = 0; nn < 32; nn++) {
            float4 kf = *(const float4*)(&KsT[nn][ty * 4]);
            float4 vf = *(const float4*)(&VsT[nn][tx * 4]);
            float ka[4] = {kf.x, kf.y, kf.z, kf.w};
            float va[4] = {vf.x, vf.y, vf.z, vf.w};
#pragma unroll
            for (int i = 0; i < 4; i++)
#pragma unroll
                for (int j = 0; j < 4; j++)
                    acc[i][j] += ka[i] * va[j];
        }
        __syncthreads();
    }

    float* kvout = g_kv + (size_t)tbh * DD * DD;
#pragma unroll
    for (int i = 0; i < 4; i++) {
        float4 r = {acc[i][0], acc[i][1], acc[i][2], acc[i][3]};
        *(float4*)(kvout + (size_t)(ty * 4 + i) * DD + tx * 4) = r;
    }
}

// ---------------------------------------------------------------------------
// Fused attention output + LIF. Block (n-tile 64, bh), loop t.
// att = 0.125 * sum_d q[d,n]*kv[d,e]  (exact: integers scaled by 2^-3),
// then LIF (v carried in registers across t) -> spikes to g_Sa.
// ---------------------------------------------------------------------------
__global__ __launch_bounds__(256)
void attn_lif_kernel()
{
    const int bh = blockIdx.y;       // 0..127 : b = bh>>3, h = bh&7
    const int b = bh >> 3;
    const int h = bh & 7;
    const int n0 = blockIdx.x * 64;

    __shared__ __align__(16) float kvs[DD][DD + 4];
    __shared__ __align__(16) float Qs[16][64];

    const int tid = threadIdx.x;
    const int tx = tid & 15, ty = tid >> 4;

    float v[4][4];
#pragma unroll
    for (int i = 0; i < 4; i++)
#pragma unroll
        for (int j = 0; j < 4; j++) v[i][j] = 0.f;

    for (int t = 0; t < TT; t++) {
        const int tb = t * BB + b;
        const float* Q_ = g_S + ((size_t)tb * CC + h * DD) * NN;
        const float* kvp = g_kv + (size_t)(t * 128 + bh) * DD * DD;

#pragma unroll
        for (int r = 0; r < 4; r++) {
            int fid = r * 256 + tid;
            int dd = fid >> 4;
            int eg = (fid & 15) * 4;
            float4 vv = *(const float4*)(kvp + (size_t)dd * DD + eg);
            *(float4*)(&kvs[dd][eg]) = vv;
        }
        __syncthreads();

        float acc[4][4] = {};
        for (int d0 = 0; d0 < DD; d0 += 16) {
            int qr = tid >> 4;
            int qc = (tid & 15) * 4;
            float4 qv = *(const float4*)(Q_ + (size_t)(d0 + qr) * NN + n0 + qc);
            *(float4*)(&Qs[qr][qc]) = qv;
            __syncthreads();
#pragma unroll
            for (int kk = 0; kk < 16; kk++) {
                float4 qf = *(const float4*)(&Qs[kk][tx * 4]);
                float4 kf = *(const float4*)(&kvs[d0 + kk][ty * 4]);
                float qa[4] = {qf.x, qf.y, qf.z, qf.w};
                float ka[4] = {kf.x, kf.y, kf.z, kf.w};
#pragma unroll
                for (int i = 0; i < 4; i++)
#pragma unroll
                    for (int j = 0; j < 4; j++)
                        acc[i][j] += ka[i] * qa[j];
            }
            __syncthreads();
        }

        // LIF on att = acc * 0.125 (exact), write spikes
#pragma unroll
        for (int i = 0; i < 4; i++) {
            const int e = ty * 4 + i;
            float4 r;
#pragma unroll
            for (int j = 0; j < 4; j++) {
                float xx = acc[i][j] * 0.125f;
                float vv = v[i][j];
                vv = vv + (xx - vv) * 0.5f;
                float s = (vv >= VTH) ? 1.f : 0.f;
                v[i][j] = (s != 0.f) ? 0.f : vv;
                ((float*)&r)[j] = s;
            }
            *(float4*)(g_Sa + ((size_t)tb * CC + h * DD + e) * NN + n0 + tx * 4) = r;
        }
    }
}

// ---------------------------------------------------------------------------
// Fused proj conv GEMM + connecting LIF (identity shortcut) -> final spikes.
// Block (o-tile 64, n-tile 64, b), loop t; v carried in registers.
// GEMM inner loop bit-exact sequential k order.
// ---------------------------------------------------------------------------
__global__ __launch_bounds__(256)
void proj_connlif_kernel(const float* __restrict__ x,
                         const float* __restrict__ Wp,
                         const float* __restrict__ bp,
                         float* __restrict__ out)
{
    __shared__ __align__(16) float Xs[16][64];
    __shared__ __align__(16) float Ws[16][68];

    const int b = blockIdx.z;
    const int n0 = blockIdx.x * 64;
    const int o0 = blockIdx.y * 64;

    const int tid = threadIdx.x;
    const int tx = tid & 15, ty = tid >> 4;

    const int xr = tid >> 4;
    const int xc = (tid & 15) * 4;
    const int wo = tid >> 2;
    const int wk = (tid & 3) * 4;

    float bb[4];
#pragma unroll
    for (int i = 0; i < 4; i++) bb[i] = bp[o0 + ty * 4 + i];

    float v[4][4];
#pragma unroll
    for (int i = 0; i < 4; i++)
#pragma unroll
        for (int j = 0; j < 4; j++) v[i][j] = 0.f;

    for (int t = 0; t < TT; t++) {
        const size_t tbofs = ((size_t)(t * BB + b)) * CC * NN;
        const float* S = g_Sa + tbofs;

        float acc[4][4];
#pragma unroll
        for (int i = 0; i < 4; i++)
#pragma unroll
            for (int j = 0; j < 4; j++) acc[i][j] = 0.f;

        for (int c0 = 0; c0 < CC; c0 += 16) {
            float4 xv = *(const float4*)(S + (size_t)(c0 + xr) * NN + n0 + xc);
            *(float4*)(&Xs[xr][xc]) = xv;
            float4 wv = *(const float4*)(Wp + (size_t)(o0 + wo) * CC + c0 + wk);
            Ws[wk + 0][wo] = wv.x;
            Ws[wk + 1][wo] = wv.y;
            Ws[wk + 2][wo] = wv.z;
            Ws[wk + 3][wo] = wv.w;
            __syncthreads();
#pragma unroll
            for (int kk = 0; kk < 16; kk++) {
                float4 xf = *(const float4*)(&Xs[kk][tx * 4]);
                float4 wf = *(const float4*)(&Ws[kk][ty * 4]);
                float xfa[4] = {xf.x, xf.y, xf.z, xf.w};
                float wfa[4] = {wf.x, wf.y, wf.z, wf.w};
#pragma unroll
                for (int i = 0; i < 4; i++)
#pragma unroll
                    for (int j = 0; j < 4; j++)
                        acc[i][j] += wfa[i] * xfa[j];
            }
            __syncthreads();
        }

        // conn-LIF epilogue: p = acc + bias; chg = p + x; LIF; write spikes
#pragma unroll
        for (int i = 0; i < 4; i++) {
            const int o = o0 + ty * 4 + i;
            const size_t row = tbofs + (size_t)o * NN + n0 + tx * 4;
            float4 xs = *(const float4*)(x + row);
            float xa[4] = {xs.x, xs.y, xs.z, xs.w};
            float4 r;
#pragma unroll
            for (int j = 0; j < 4; j++) {
                float p = acc[i][j] + bb[i];
                float chg = p + xa[j];
                float vv = v[i][j];
                vv = vv + (chg - vv) * 0.5f;
                float s = (vv >= VTH) ? 1.f : 0.f;
                v[i][j] = (s != 0.f) ? 0.f : vv;
                ((float*)&r)[j] = s;
            }
            *(float4*)(out + row) = r;
        }
    }
}

// ---------------------------------------------------------------------------
extern "C" void kernel_launch(void* const* d_in, const int* in_sizes, int n_in,
                              void* d_out, int out_size)
{
    const float* x  = (const float*)d_in[0];
    const float* Wq = (const float*)d_in[1];
    const float* bq = (const float*)d_in[2];
    const float* Wk = (const float*)d_in[3];
    const float* bk = (const float*)d_in[4];
    const float* Wv = (const float*)d_in[5];
    const float* bv = (const float*)d_in[6];
    const float* Wp = (const float*)d_in[7];
    const float* bp = (const float*)d_in[8];
    float* out = (float*)d_out;

    const int QKV_SMEM = (1024 + 3264 + 3 * 4096) * 4;  // 66304 bytes
    cudaFuncSetAttribute(qkv_lif_kernel,
                         cudaFuncAttributeMaxDynamicSharedMemorySize, QKV_SMEM);

    // 1. fused QKV conv GEMM + LIF (bit-exact sequential-k chains)
    qkv_lif_kernel<<<dim3(NN / 64, CC / 64, BB), 256, QKV_SMEM>>>(
        x, Wq, Wk, Wv, bq, bk, bv);
    // 2. kv = K^T V per head (exact integer counts)
    kv_kernel<<<TT * BB * HEADS, 256>>>();
    // 3. fused attention output + LIF (exact values)
    attn_lif_kernel<<<dim3(NN / 64, BB * HEADS), 256>>>();
    // 4. fused proj conv GEMM + connecting LIF -> final spikes
    proj_connlif_kernel<<<dim3(NN / 64, CC / 64, BB), 256>>>(x, Wp, bp, out);
}

// round 8
// speedup vs baseline: 1.7247x; 1.2063x over previous
#include <cuda_runtime.h>
#include <cstdint>

// Problem shape (fixed): x [T,B,C,H,W], T=4,B=16,C=512,H=W=32 -> N=1024
#define TT 4
#define BB 16
#define CC 512
#define NN 1024
#define HEADS 8
#define DD 64
#define VTH 1.0f

#define BCN  ((size_t)BB * CC * NN)          // 8,388,608
#define TBCN ((size_t)TT * BB * CC * NN)     // 33,554,432

// ---------------- scratch (static device globals; no runtime allocation) ----
__device__ float g_S[3ull * TBCN];   // spikes q,k,v
__device__ float g_Sa[TBCN];         // attention spikes
__device__ float g_kv[(size_t)TT * BB * HEADS * DD * DD];
__device__ float g_Wt[4ull * CC * CC];  // pre-transposed weights [mat][c][o]

// ===================== helpers =============================================
__device__ __forceinline__ uint32_t smem_u32(const void* p) {
    uint32_t a;
    asm("{ .reg .u64 t; cvta.to.shared.u64 t, %1; cvt.u32.u64 %0, t; }"
        : "=r"(a) : "l"(p));
    return a;
}
__device__ __forceinline__ void cp_async16(uint32_t dst, const void* src) {
    asm volatile("cp.async.cg.shared.global [%0], [%1], 16;"
                 :: "r"(dst), "l"(src));
}
#define CP_COMMIT() asm volatile("cp.async.commit_group;" ::: "memory")
#define CP_WAIT1()  asm volatile("cp.async.wait_group 1;" ::: "memory")
#define CP_WAIT0()  asm volatile("cp.async.wait_group 0;" ::: "memory")

// ---------------------------------------------------------------------------
// W transpose: Wt[mat][c][o] = W[mat][o][c]   (one-shot, 4 MB)
// ---------------------------------------------------------------------------
__global__ void wtrans_kernel(const float* __restrict__ W0, const float* __restrict__ W1,
                              const float* __restrict__ W2, const float* __restrict__ W3)
{
    __shared__ float tile[32][33];
    const int mat = blockIdx.z;
    const float* W = (mat == 0) ? W0 : (mat == 1) ? W1 : (mat == 2) ? W2 : W3;
    const int o0 = blockIdx.x * 32, c0 = blockIdx.y * 32;
    const int t = threadIdx.x;
    const int r = t >> 3, cg = (t & 7) * 4;
    {
        float4 v = *(const float4*)(W + (size_t)(o0 + r) * CC + c0 + cg);
        tile[r][cg + 0] = v.x; tile[r][cg + 1] = v.y;
        tile[r][cg + 2] = v.z; tile[r][cg + 3] = v.w;
    }
    __syncthreads();
    {
        float4 v;
        v.x = tile[cg + 0][r]; v.y = tile[cg + 1][r];
        v.z = tile[cg + 2][r]; v.w = tile[cg + 3][r];
        *(float4*)(g_Wt + (size_t)mat * CC * CC + (size_t)(c0 + r) * CC + o0 + cg) = v;
    }
}

// ---------------------------------------------------------------------------
// Uniform fused conv1x1 GEMM + LIF.
// Y[o,n] = sum_c W[o,c]*In[c,n] + bias[o] ; LIF over t (v in smem)
// CONN=1: charge = Y + x (shortcut), output -> Out (final spikes)
// CONN=0: output -> Out + mat*TBCN  (q,k,v spikes)
// Tile 128(o) x 128(n), BK=16, 256 thr, 8x8 microtile split {lo,hi+64}.
// 2-stage cp.async double buffer; W from pre-transposed g_Wt (no transpose).
// Accumulation per output is sequential over c (bit-exact vs reference chain).
// Dynamic smem: Xs 2x[16][128] + Ws 2x[16][128] + Vs[64][256] = 96 KB.
// ---------------------------------------------------------------------------
template <int CONN>
__global__ __launch_bounds__(256, 2)
void gemm_lif(const float* __restrict__ In,
              const float* __restrict__ WtAll, int matofs,
              const float* __restrict__ b0, const float* __restrict__ b1,
              const float* __restrict__ b2,
              const float* __restrict__ xsc,
              float* __restrict__ Out)
{
    extern __shared__ float sm[];
    float* Xs = sm;            // 2 stages x [16][128]
    float* Ws = sm + 4096;     // 2 stages x [16][128]
    float* Vs = sm + 8192;     // [64][256]
    const uint32_t xs_b = smem_u32(Xs), ws_b = smem_u32(Ws);

    const int tid = threadIdx.x, tx = tid & 15, ty = tid >> 4;
    const int z = blockIdx.z;
    const int mat = CONN ? 0 : (z >> 4);
    const int b = CONN ? z : (z & 15);
    const int n0 = blockIdx.x * 128, o0 = blockIdx.y * 128;

    const float* Wt = WtAll + (size_t)(matofs + mat) * CC * CC;
    const float* bias = (mat == 0) ? b0 : (mat == 1) ? b1 : b2;
    float* outb = Out + (CONN ? 0 : (size_t)mat * TBCN);

    float bb[8];
#pragma unroll
    for (int i = 0; i < 4; i++) {
        bb[i] = bias[o0 + ty * 4 + i];
        bb[4 + i] = bias[o0 + 64 + ty * 4 + i];
    }

    const int lr = tid >> 4;           // fill row 0..15
    const int lc = (tid & 15) * 8;     // fill col base (8 floats = 2x16B)

    for (int t = 0; t < TT; t++) {
        const float* Xb = In + (size_t)(t * BB + b) * CC * NN;

        float acc[8][8];
#pragma unroll
        for (int i = 0; i < 8; i++)
#pragma unroll
            for (int j = 0; j < 8; j++) acc[i][j] = 0.f;

        // prologue fill k-tile 0
        {
            const float* xp = Xb + (size_t)lr * NN + n0 + lc;
            uint32_t xd = xs_b + (uint32_t)(lr * 128 + lc) * 4;
            cp_async16(xd, xp); cp_async16(xd + 16, xp + 4);
            const float* wp = Wt + (size_t)lr * CC + o0 + lc;
            uint32_t wd = ws_b + (uint32_t)(lr * 128 + lc) * 4;
            cp_async16(wd, wp); cp_async16(wd + 16, wp + 4);
            CP_COMMIT();
        }

        for (int kt = 0; kt < 32; kt++) {
            if (kt < 31) {
                const int s = (kt + 1) & 1;
                const int k0 = (kt + 1) * 16;
                const float* xp = Xb + (size_t)(k0 + lr) * NN + n0 + lc;
                uint32_t xd = xs_b + (uint32_t)(s * 2048 + lr * 128 + lc) * 4;
                cp_async16(xd, xp); cp_async16(xd + 16, xp + 4);
                const float* wp = Wt + (size_t)(k0 + lr) * CC + o0 + lc;
                uint32_t wd = ws_b + (uint32_t)(s * 2048 + lr * 128 + lc) * 4;
                cp_async16(wd, wp); cp_async16(wd + 16, wp + 4);
                CP_COMMIT();
                CP_WAIT1();
            } else {
                CP_WAIT0();
            }
            __syncthreads();

            const float* Xst = Xs + (kt & 1) * 2048;
            const float* Wst = Ws + (kt & 1) * 2048;
#pragma unroll
            for (int kk = 0; kk < 16; kk++) {
                float4 xa = *(const float4*)(Xst + kk * 128 + tx * 4);
                float4 xc = *(const float4*)(Xst + kk * 128 + 64 + tx * 4);
                float4 wa = *(const float4*)(Wst + kk * 128 + ty * 4);
                float4 wc = *(const float4*)(Wst + kk * 128 + 64 + ty * 4);
                float xv[8] = {xa.x, xa.y, xa.z, xa.w, xc.x, xc.y, xc.z, xc.w};
                float wv[8] = {wa.x, wa.y, wa.z, wa.w, wc.x, wc.y, wc.z, wc.w};
#pragma unroll
                for (int i = 0; i < 8; i++)
#pragma unroll
                    for (int j = 0; j < 8; j++)
                        acc[i][j] += wv[i] * xv[j];
            }
            __syncthreads();
        }

        // epilogue: bias (+shortcut) + LIF + spike write; v persists in smem
        const size_t tbofs = (size_t)(t * BB + b) * CC * NN;
#pragma unroll
        for (int i = 0; i < 8; i++) {
            const int o = o0 + ((i < 4) ? (ty * 4 + i) : (64 + ty * 4 + i - 4));
            const size_t rowb = tbofs + (size_t)o * NN + n0;
#pragma unroll
            for (int hf = 0; hf < 2; hf++) {
                const int nc = hf ? (64 + tx * 4) : (tx * 4);
                float4 xs4;
                if (CONN) xs4 = *(const float4*)(xsc + rowb + nc);
                float4 r;
#pragma unroll
                for (int j = 0; j < 4; j++) {
                    const int vi = i * 8 + hf * 4 + j;
                    float v = (t == 0) ? 0.f : Vs[vi * 256 + tid];
                    float p = acc[i][hf * 4 + j] + bb[i];
                    float chg = CONN ? (p + ((const float*)&xs4)[j]) : p;
                    v = v + (chg - v) * 0.5f;
                    float s = (v >= VTH) ? 1.f : 0.f;
                    Vs[vi * 256 + tid] = (s != 0.f) ? 0.f : v;
                    ((float*)&r)[j] = s;
                }
                *(float4*)(outb + rowb + nc) = r;
            }
        }
    }
}

// ---------------------------------------------------------------------------
// kv[tbh][d][e] = sum_n Sk[h*64+d, n] * Sv[h*64+e, n]   (exact integer counts)
// ---------------------------------------------------------------------------
__global__ __launch_bounds__(256)
void kv_kernel()
{
    const int tbh = blockIdx.x;
    const int tb = tbh >> 3;
    const int h = tbh & 7;
    const float* K_ = g_S + 1ull * TBCN + ((size_t)tb * CC + h * DD) * NN;
    const float* V_ = g_S + 2ull * TBCN + ((size_t)tb * CC + h * DD) * NN;

    __shared__ __align__(16) float KsT[32][DD + 4];
    __shared__ __align__(16) float VsT[32][DD + 4];

    const int tid = threadIdx.x;
    const int tx = tid & 15, ty = tid >> 4;
    float acc[4][4] = {};

    for (int nb = 0; nb < NN; nb += 32) {
#pragma unroll
        for (int r = 0; r < 2; r++) {
            int fid = r * 256 + tid;
            int dd = fid >> 3;
            int ng = (fid & 7) * 4;
            float4 k4 = *(const float4*)(K_ + (size_t)dd * NN + nb + ng);
            KsT[ng + 0][dd] = k4.x; KsT[ng + 1][dd] = k4.y;
            KsT[ng + 2][dd] = k4.z; KsT[ng + 3][dd] = k4.w;
            float4 v4 = *(const float4*)(V_ + (size_t)dd * NN + nb + ng);
            VsT[ng + 0][dd] = v4.x; VsT[ng + 1][dd] = v4.y;
            VsT[ng + 2][dd] = v4.z; VsT[ng + 3][dd] = v4.w;
        }
        __syncthreads();
#pragma unroll
        for (int nn = 0; nn < 32; nn++) {
            float4 kf = *(const float4*)(&KsT[nn][ty * 4]);
            float4 vf = *(const float4*)(&VsT[nn][tx * 4]);
            float ka[4] = {kf.x, kf.y, kf.z, kf.w};
            float va[4] = {vf.x, vf.y, vf.z, vf.w};
#pragma unroll
            for (int i = 0; i < 4; i++)
#pragma unroll
                for (int j = 0; j < 4; j++)
                    acc[i][j] += ka[i] * va[j];
        }
        __syncthreads();
    }

    float* kvout = g_kv + (size_t)tbh * DD * DD;
#pragma unroll
    for (int i = 0; i < 4; i++) {
        float4 r = {acc[i][0], acc[i][1], acc[i][2], acc[i][3]};
        *(float4*)(kvout + (size_t)(ty * 4 + i) * DD + tx * 4) = r;
    }
}

// ---------------------------------------------------------------------------
// Fused attention output + LIF. Block (n-tile 64, bh), loop t.
// ---------------------------------------------------------------------------
__global__ __launch_bounds__(256)
void attn_lif_kernel()
{
    const int bh = blockIdx.y;
    const int b = bh >> 3;
    const int h = bh & 7;
    const int n0 = blockIdx.x * 64;

    __shared__ __align__(16) float kvs[DD][DD + 4];
    __shared__ __align__(16) float Qs[16][64];

    const int tid = threadIdx.x;
    const int tx = tid & 15, ty = tid >> 4;

    float v[4][4];
#pragma unroll
    for (int i = 0; i < 4; i++)
#pragma unroll
        for (int j = 0; j < 4; j++) v[i][j] = 0.f;

    for (int t = 0; t < TT; t++) {
        const int tb = t * BB + b;
        const float* Q_ = g_S + ((size_t)tb * CC + h * DD) * NN;
        const float* kvp = g_kv + (size_t)(t * 128 + bh) * DD * DD;

#pragma unroll
        for (int r = 0; r < 4; r++) {
            int fid = r * 256 + tid;
            int dd = fid >> 4;
            int eg = (fid & 15) * 4;
            float4 vv = *(const float4*)(kvp + (size_t)dd * DD + eg);
            *(float4*)(&kvs[dd][eg]) = vv;
        }
        __syncthreads();

        float acc[4][4] = {};
        for (int d0 = 0; d0 < DD; d0 += 16) {
            int qr = tid >> 4;
            int qc = (tid & 15) * 4;
            float4 qv = *(const float4*)(Q_ + (size_t)(d0 + qr) * NN + n0 + qc);
            *(float4*)(&Qs[qr][qc]) = qv;
            __syncthreads();
#pragma unroll
            for (int kk = 0; kk < 16; kk++) {
                float4 qf = *(const float4*)(&Qs[kk][tx * 4]);
                float4 kf = *(const float4*)(&kvs[d0 + kk][ty * 4]);
                float qa[4] = {qf.x, qf.y, qf.z, qf.w};
                float ka[4] = {kf.x, kf.y, kf.z, kf.w};
#pragma unroll
                for (int i = 0; i < 4; i++)
#pragma unroll
                    for (int j = 0; j < 4; j++)
                        acc[i][j] += ka[i] * qa[j];
            }
            __syncthreads();
        }

#pragma unroll
        for (int i = 0; i < 4; i++) {
            const int e = ty * 4 + i;
            float4 r;
#pragma unroll
            for (int j = 0; j < 4; j++) {
                float xx = acc[i][j] * 0.125f;
                float vv = v[i][j];
                vv = vv + (xx - vv) * 0.5f;
                float s = (vv >= VTH) ? 1.f : 0.f;
                v[i][j] = (s != 0.f) ? 0.f : vv;
                ((float*)&r)[j] = s;
            }
            *(float4*)(g_Sa + ((size_t)tb * CC + h * DD + e) * NN + n0 + tx * 4) = r;
        }
    }
}

// ---------------------------------------------------------------------------
extern "C" void kernel_launch(void* const* d_in, const int* in_sizes, int n_in,
                              void* d_out, int out_size)
{
    const float* x  = (const float*)d_in[0];
    const float* Wq = (const float*)d_in[1];
    const float* bq = (const float*)d_in[2];
    const float* Wk = (const float*)d_in[3];
    const float* bk = (const float*)d_in[4];
    const float* Wv = (const float*)d_in[5];
    const float* bv = (const float*)d_in[6];
    const float* Wp = (const float*)d_in[7];
    const float* bp = (const float*)d_in[8];
    float* out = (float*)d_out;

    void *pS, *pSa, *pWt;
    cudaGetSymbolAddress(&pS, g_S);
    cudaGetSymbolAddress(&pSa, g_Sa);
    cudaGetSymbolAddress(&pWt, g_Wt);

    const int GL_SMEM = (8192 + 16384) * 4;  // 98304 bytes
    cudaFuncSetAttribute(gemm_lif<0>, cudaFuncAttributeMaxDynamicSharedMemorySize, GL_SMEM);
    cudaFuncSetAttribute(gemm_lif<1>, cudaFuncAttributeMaxDynamicSharedMemorySize, GL_SMEM);

    // 1. one-shot weight transpose (Wt[c][o])
    wtrans_kernel<<<dim3(16, 16, 4), 256>>>(Wq, Wk, Wv, Wp);
    // 2. fused QKV conv GEMM + LIF (q,k,v in one launch; bit-exact chains)
    gemm_lif<0><<<dim3(8, 4, 48), 256, GL_SMEM>>>(
        x, (const float*)pWt, 0, bq, bk, bv, nullptr, (float*)pS);
    // 3. kv = K^T V per head (exact integer counts)
    kv_kernel<<<TT * BB * HEADS, 256>>>();
    // 4. fused attention output + LIF
    attn_lif_kernel<<<dim3(NN / 64, BB * HEADS), 256>>>();
    // 5. fused proj conv GEMM + connecting LIF -> final spikes
    gemm_lif<1><<<dim3(8, 4, 16), 256, GL_SMEM>>>(
        (const float*)pSa, (const float*)pWt, 3, bp, bp, bp, x, out);
}